// round 3
// baseline (speedup 1.0000x reference)
#include <cuda_runtime.h>

// ---------------------------------------------------------------------------
// NeuralNetGlobalHammerWiener: fused pre-MLP(tanh) -> complex FIR(32) -> post-MLP(relu)
// Single kernel, one pass over HBM.
//
// Inputs (metadata order):
//  0 x_real  [16,1,262144,1] f32
//  1 x_imag  [16,1,262144,1] f32
//  2 w1_pre  [1,8]
//  3 w2_pre  [8,1]
//  4 w_fir_r [32]
//  5 w_fir_i [32]
//  6 w1_post [1,8]
//  7 b1_post [8]
//  8 w2_post [8,1]
//  9 b2_post [1]
// Output: [16,1,262113,2] f32 (yr, yi interleaved)
// ---------------------------------------------------------------------------

#define FILTER_LEN 32
#define HALO       (FILTER_LEN - 1)          // 31
#define W_IN       262144
#define W_OUT      (W_IN - HALO)             // 262113
#define BATCH      16
#define THREADS    256
#define T_OUT      8
#define TILE       (THREADS * T_OUT)         // 2048
#define TILES_ROW  ((W_OUT + TILE - 1) / TILE)  // 128
#define NLOAD      (TILE + HALO)             // 2079
// padded index: one extra float2 per 8 elements -> lane stride 9 (conflict-free LDS.64)
#define PAD(i)     ((i) + ((i) >> 3))
#define SPAD       (PAD(NLOAD - 1) + 1)      // 2338

#define OUT_SCALE  0.17782794100389228f      // sqrt(10^(-15/10))
#define LOG2E      1.4426950408889634f

// ---- packed f32x2 helpers (Blackwell FFMA2 path) ----
__device__ __forceinline__ unsigned long long pk2(float lo, float hi) {
    unsigned long long r;
    asm("mov.b64 %0, {%1, %2};" : "=l"(r) : "f"(lo), "f"(hi));
    return r;
}
__device__ __forceinline__ void upk2(unsigned long long v, float& lo, float& hi) {
    asm("mov.b64 {%0, %1}, %2;" : "=f"(lo), "=f"(hi) : "l"(v));
}
__device__ __forceinline__ unsigned long long ffma2(unsigned long long a,
                                                    unsigned long long b,
                                                    unsigned long long c) {
    unsigned long long d;
    asm("fma.rn.f32x2 %0, %1, %2, %3;" : "=l"(d) : "l"(a), "l"(b), "l"(c));
    return d;
}

__global__ void __launch_bounds__(THREADS)
hammer_wiener_kernel(const float* __restrict__ x_real,
                     const float* __restrict__ x_imag,
                     const float* __restrict__ w1_pre,
                     const float* __restrict__ w2_pre,
                     const float* __restrict__ w_fir_r,
                     const float* __restrict__ w_fir_i,
                     const float* __restrict__ w1_post,
                     const float* __restrict__ b1_post,
                     const float* __restrict__ w2_post,
                     const float* __restrict__ b2_post,
                     float2* __restrict__ out) {
    __shared__ float2 s_xh[SPAD];        // packed (xh_r, xh_i), padded
    __shared__ float2 s_wrb[FILTER_LEN]; // (wr, wr) broadcast-packed
    __shared__ float2 s_wib[FILTER_LEN]; // (wi, wi)
    __shared__ float  s_w1a[8];          // 2 * w1_pre * log2(e)  (folded for exp2)
    __shared__ float  s_w2a[8];
    __shared__ float  s_w1b[8];
    __shared__ float  s_b1b[8];
    __shared__ float  s_w2b[8];
    __shared__ float  s_b2b;

    const int tid   = threadIdx.x;
    const int b     = blockIdx.y;
    const int tile0 = blockIdx.x * TILE;

    // ---- load params into shared ----
    if (tid < FILTER_LEN) {
        float wr = w_fir_r[tid];
        float wi = w_fir_i[tid];
        s_wrb[tid] = make_float2(wr, wr);
        s_wib[tid] = make_float2(wi, wi);
    }
    if (tid >= 32 && tid < 40) {
        int j = tid - 32;
        s_w1a[j] = 2.0f * LOG2E * w1_pre[j];
        s_w2a[j] = w2_pre[j];
        s_w1b[j] = w1_post[j];
        s_b1b[j] = b1_post[j];
        s_w2b[j] = w2_post[j];
    }
    if (tid == 40) s_b2b = b2_post[0];
    __syncthreads();

    // ---- stage A: pre nonlinearity -> xh into shared (with halo) ----
    const float* __restrict__ xr_row = x_real + (size_t)b * W_IN;
    const float* __restrict__ xi_row = x_imag + (size_t)b * W_IN;

    for (int i = tid; i < NLOAD; i += THREADS) {
        int g = tile0 + i;
        float r = 0.0f, im = 0.0f;
        if (g < W_IN) { r = xr_row[g]; im = xi_row[g]; }
        float m2  = fmaf(r, r, im * im);
        float inv = rsqrtf(m2);
        bool  nz  = (m2 > 0.0f);
        float mag = nz ? m2 * inv : 0.0f;
        float acc = 0.0f;
#pragma unroll
        for (int j = 0; j < 8; j++) {
            // tanh(t) = 1 - 2/(exp(2t)+1); exp folded into exp2 with scaled weight
            float e  = exp2f(mag * s_w1a[j]);
            float th = 1.0f - __fdividef(2.0f, e + 1.0f);
            acc = fmaf(th, s_w2a[j], acc);
        }
        float sc = nz ? acc * inv : 0.0f;           // m / mag
        s_xh[PAD(i)] = make_float2(sc * r, sc * im);
    }
    __syncthreads();

    // ---- stage B: 32-tap complex FIR with packed f32x2 accumulators ----
    // acc1 = (sum wr*xr, sum wr*xi), acc2 = (sum wi*xr, sum wi*xi)
    // zr = acc1.lo - acc2.hi ; zi = acc1.hi + acc2.lo
    const int base = tid * T_OUT;

    unsigned long long A[T_OUT + HALO];   // 39 packed complex window values
#pragma unroll
    for (int i = 0; i < T_OUT + HALO; i++) {
        int idx = base + i;
        A[i] = *reinterpret_cast<const unsigned long long*>(&s_xh[PAD(idx)]);
    }

    unsigned long long acc1[T_OUT], acc2[T_OUT];
#pragma unroll
    for (int j = 0; j < T_OUT; j++) { acc1[j] = 0ULL; acc2[j] = 0ULL; }

#pragma unroll
    for (int k = 0; k < FILTER_LEN; k++) {
        unsigned long long wrb = *reinterpret_cast<const unsigned long long*>(&s_wrb[k]);
        unsigned long long wib = *reinterpret_cast<const unsigned long long*>(&s_wib[k]);
#pragma unroll
        for (int j = 0; j < T_OUT; j++) {
            acc1[j] = ffma2(wrb, A[k + j], acc1[j]);
            acc2[j] = ffma2(wib, A[k + j], acc2[j]);
        }
    }

    // ---- stage C: post nonlinearity + store ----
    const size_t out_base = (size_t)b * W_OUT;
#pragma unroll
    for (int j = 0; j < T_OUT; j++) {
        float a1lo, a1hi, a2lo, a2hi;
        upk2(acc1[j], a1lo, a1hi);
        upk2(acc2[j], a2lo, a2hi);
        float zr = a1lo - a2hi;
        float zi = a1hi + a2lo;

        float m2  = fmaf(zr, zr, zi * zi);
        float inv = rsqrtf(m2);
        bool  nz  = (m2 > 0.0f);
        float zmag = nz ? m2 * inv : 0.0f;
        float cr   = nz ? zr * inv : 1.0f;   // cos(atan2(zi,zr)); atan2(0,0)=0 -> cos=1
        float ci   = nz ? zi * inv : 0.0f;

        float zm = s_b2b;
#pragma unroll
        for (int f = 0; f < 8; f++) {
            float g = fmaf(zmag, s_w1b[f], s_b1b[f]);
            g = fmaxf(g, 0.0f);
            zm = fmaf(g, s_w2b[f], zm);
        }
        float sm = OUT_SCALE * zm;

        int n = tile0 + base + j;
        if (n < W_OUT) {
            out[out_base + n] = make_float2(sm * cr, sm * ci);
        }
    }
}

extern "C" void kernel_launch(void* const* d_in, const int* in_sizes, int n_in,
                              void* d_out, int out_size) {
    (void)in_sizes; (void)n_in; (void)out_size;
    const float* x_real   = (const float*)d_in[0];
    const float* x_imag   = (const float*)d_in[1];
    const float* w1_pre   = (const float*)d_in[2];
    const float* w2_pre   = (const float*)d_in[3];
    const float* w_fir_r  = (const float*)d_in[4];
    const float* w_fir_i  = (const float*)d_in[5];
    const float* w1_post  = (const float*)d_in[6];
    const float* b1_post  = (const float*)d_in[7];
    const float* w2_post  = (const float*)d_in[8];
    const float* b2_post  = (const float*)d_in[9];

    dim3 grid(TILES_ROW, BATCH);
    hammer_wiener_kernel<<<grid, THREADS>>>(
        x_real, x_imag, w1_pre, w2_pre, w_fir_r, w_fir_i,
        w1_post, b1_post, w2_post, b2_post, (float2*)d_out);
}

// round 4
// speedup vs baseline: 1.2828x; 1.2828x over previous
#include <cuda_runtime.h>

// ---------------------------------------------------------------------------
// Fused pre-MLP(tanh) -> complex FIR(32) -> post-MLP(relu), one HBM pass.
// R4: ring-buffer FIR window (8 live elems, not 39) + reg cap 64 for occupancy,
//     tanh.approx.f32, float4 input loads, 128-thread blocks.
// ---------------------------------------------------------------------------

#define FILTER_LEN 32
#define HALO       (FILTER_LEN - 1)          // 31
#define W_IN       262144
#define W_OUT      (W_IN - HALO)             // 262113
#define BATCH      16
#define THREADS    128
#define T_OUT      8
#define TILE       (THREADS * T_OUT)         // 1024
#define TILES_ROW  ((W_OUT + TILE - 1) / TILE)  // 256
#define NLOAD      (TILE + HALO)             // 1055
// padded index: one extra float2 per 8 elements -> conflict-free LDS.64
#define PAD(i)     ((i) + ((i) >> 3))
#define SPAD       (PAD(NLOAD - 1) + 1)

#define OUT_SCALE  0.17782794100389228f      // sqrt(10^(-15/10))

// ---- packed f32x2 helpers (Blackwell FFMA2 path) ----
__device__ __forceinline__ void upk2(unsigned long long v, float& lo, float& hi) {
    asm("mov.b64 {%0, %1}, %2;" : "=f"(lo), "=f"(hi) : "l"(v));
}
__device__ __forceinline__ unsigned long long ffma2(unsigned long long a,
                                                    unsigned long long b,
                                                    unsigned long long c) {
    unsigned long long d;
    asm("fma.rn.f32x2 %0, %1, %2, %3;" : "=l"(d) : "l"(a), "l"(b), "l"(c));
    return d;
}
__device__ __forceinline__ float tanh_approx(float x) {
    float y;
    asm("tanh.approx.f32 %0, %1;" : "=f"(y) : "f"(x));
    return y;
}
__device__ __forceinline__ unsigned long long lds64(const float2* p) {
    return *reinterpret_cast<const unsigned long long*>(p);
}

__global__ void __launch_bounds__(THREADS, 8)
hammer_wiener_kernel(const float* __restrict__ x_real,
                     const float* __restrict__ x_imag,
                     const float* __restrict__ w1_pre,
                     const float* __restrict__ w2_pre,
                     const float* __restrict__ w_fir_r,
                     const float* __restrict__ w_fir_i,
                     const float* __restrict__ w1_post,
                     const float* __restrict__ b1_post,
                     const float* __restrict__ w2_post,
                     const float* __restrict__ b2_post,
                     float2* __restrict__ out) {
    __shared__ float2 s_xh[SPAD];        // packed (xh_r, xh_i), padded
    __shared__ float2 s_wrb[FILTER_LEN]; // (wr, wr)
    __shared__ float2 s_wib[FILTER_LEN]; // (wi, wi)
    __shared__ float  s_w1a[8];
    __shared__ float  s_w2a[8];
    __shared__ float  s_w1b[8];
    __shared__ float  s_b1b[8];
    __shared__ float  s_w2b[8];
    __shared__ float  s_b2b;

    const int tid   = threadIdx.x;
    const int b     = blockIdx.y;
    const int tile0 = blockIdx.x * TILE;

    // ---- params -> shared ----
    if (tid < FILTER_LEN) {
        float wr = w_fir_r[tid];
        float wi = w_fir_i[tid];
        s_wrb[tid] = make_float2(wr, wr);
        s_wib[tid] = make_float2(wi, wi);
    }
    if (tid >= 32 && tid < 40) {
        int j = tid - 32;
        s_w1a[j] = w1_pre[j];
        s_w2a[j] = w2_pre[j];
        s_w1b[j] = w1_post[j];
        s_b1b[j] = b1_post[j];
        s_w2b[j] = w2_post[j];
    }
    if (tid == 40) s_b2b = b2_post[0];
    __syncthreads();

    // ---- stage A: pre nonlinearity -> xh into shared (with halo) ----
    const float* __restrict__ xr_row = x_real + (size_t)b * W_IN;
    const float* __restrict__ xi_row = x_imag + (size_t)b * W_IN;

    // main TILE elements: float4 vectorized (tile0 is 1024-aligned, always in range)
#pragma unroll
    for (int it = 0; it < TILE / (4 * THREADS); it++) {
        int t = tid + it * THREADS;                 // float4 slot
        float4 r4 = *reinterpret_cast<const float4*>(xr_row + tile0 + 4 * t);
        float4 i4 = *reinterpret_cast<const float4*>(xi_row + tile0 + 4 * t);
        float rr[4] = {r4.x, r4.y, r4.z, r4.w};
        float ii[4] = {i4.x, i4.y, i4.z, i4.w};
        int p0 = PAD(4 * t);                        // 4-group stays inside one 8-block
#pragma unroll
        for (int q = 0; q < 4; q++) {
            float r = rr[q], im = ii[q];
            float m2  = fmaf(r, r, im * im);
            float inv = rsqrtf(m2);
            bool  nz  = (m2 > 0.0f);
            float mag = nz ? m2 * inv : 0.0f;
            float acc = 0.0f;
#pragma unroll
            for (int j = 0; j < 8; j++)
                acc = fmaf(tanh_approx(mag * s_w1a[j]), s_w2a[j], acc);
            float sc = nz ? acc * inv : 0.0f;       // m / mag
            s_xh[p0 + q] = make_float2(sc * r, sc * im);
        }
    }
    // halo: 31 scalar elements, guarded
    if (tid < HALO) {
        int i = TILE + tid;
        int g = tile0 + i;
        float r = 0.0f, im = 0.0f;
        if (g < W_IN) { r = xr_row[g]; im = xi_row[g]; }
        float m2  = fmaf(r, r, im * im);
        float inv = rsqrtf(m2);
        bool  nz  = (m2 > 0.0f);
        float mag = nz ? m2 * inv : 0.0f;
        float acc = 0.0f;
#pragma unroll
        for (int j = 0; j < 8; j++)
            acc = fmaf(tanh_approx(mag * s_w1a[j]), s_w2a[j], acc);
        float sc = nz ? acc * inv : 0.0f;
        s_xh[PAD(i)] = make_float2(sc * r, sc * im);
    }
    __syncthreads();

    // ---- stage B: 32-tap complex FIR, ring-buffer window (8 live elements) ----
    // acc1 = (sum wr*xr, sum wr*xi), acc2 = (sum wi*xr, sum wi*xi)
    const int base = tid * T_OUT;

    unsigned long long Wd[8];
#pragma unroll
    for (int i = 0; i < 8; i++) Wd[i] = lds64(&s_xh[PAD(base + i)]);

    unsigned long long acc1[T_OUT], acc2[T_OUT];
#pragma unroll
    for (int j = 0; j < T_OUT; j++) { acc1[j] = 0ULL; acc2[j] = 0ULL; }

#pragma unroll
    for (int k = 0; k < FILTER_LEN; k++) {
        unsigned long long wrb = lds64(&s_wrb[k]);
        unsigned long long wib = lds64(&s_wib[k]);
#pragma unroll
        for (int j = 0; j < T_OUT; j++) {
            unsigned long long a = Wd[(k + j) & 7];
            acc1[j] = ffma2(wrb, a, acc1[j]);
            acc2[j] = ffma2(wib, a, acc2[j]);
        }
        if (k < FILTER_LEN - 1)
            Wd[k & 7] = lds64(&s_xh[PAD(base + k + 8)]);
    }

    // ---- stage C: post nonlinearity + store ----
    const size_t out_base = (size_t)b * W_OUT;
#pragma unroll
    for (int j = 0; j < T_OUT; j++) {
        float a1lo, a1hi, a2lo, a2hi;
        upk2(acc1[j], a1lo, a1hi);
        upk2(acc2[j], a2lo, a2hi);
        float zr = a1lo - a2hi;
        float zi = a1hi + a2lo;

        float m2  = fmaf(zr, zr, zi * zi);
        float inv = rsqrtf(m2);
        bool  nz  = (m2 > 0.0f);
        float zmag = nz ? m2 * inv : 0.0f;
        float cr   = nz ? zr * inv : 1.0f;   // cos(atan2(0,0)) = 1
        float ci   = nz ? zi * inv : 0.0f;

        float zm = s_b2b;
#pragma unroll
        for (int f = 0; f < 8; f++) {
            float g = fmaf(zmag, s_w1b[f], s_b1b[f]);
            g = fmaxf(g, 0.0f);
            zm = fmaf(g, s_w2b[f], zm);
        }
        float sm = OUT_SCALE * zm;

        int n = tile0 + base + j;
        if (n < W_OUT) {
            out[out_base + n] = make_float2(sm * cr, sm * ci);
        }
    }
}

extern "C" void kernel_launch(void* const* d_in, const int* in_sizes, int n_in,
                              void* d_out, int out_size) {
    (void)in_sizes; (void)n_in; (void)out_size;
    const float* x_real   = (const float*)d_in[0];
    const float* x_imag   = (const float*)d_in[1];
    const float* w1_pre   = (const float*)d_in[2];
    const float* w2_pre   = (const float*)d_in[3];
    const float* w_fir_r  = (const float*)d_in[4];
    const float* w_fir_i  = (const float*)d_in[5];
    const float* w1_post  = (const float*)d_in[6];
    const float* b1_post  = (const float*)d_in[7];
    const float* w2_post  = (const float*)d_in[8];
    const float* b2_post  = (const float*)d_in[9];

    dim3 grid(TILES_ROW, BATCH);
    hammer_wiener_kernel<<<grid, THREADS>>>(
        x_real, x_imag, w1_pre, w2_pre, w_fir_r, w_fir_i,
        w1_post, b1_post, w2_post, b2_post, (float2*)d_out);
}

// round 5
// speedup vs baseline: 1.3868x; 1.0811x over previous
#include <cuda_runtime.h>

// ---------------------------------------------------------------------------
// Fused pre-MLP(tanh) -> complex FIR(32) -> post-MLP(relu), one HBM pass.
// R5: warp-autonomous tiles (no mid-kernel __syncthreads) — each warp owns a
//     256-output chunk + halo in its own smem segment; balanced 9-samples/lane
//     front-batched loads; reg cap relaxed to ~85.
// ---------------------------------------------------------------------------

#define FILTER_LEN 32
#define HALO       (FILTER_LEN - 1)          // 31
#define W_IN       262144
#define W_OUT      (W_IN - HALO)             // 262113
#define BATCH      16
#define THREADS    128
#define WARPS      4
#define T_OUT      8
#define WTILE      256                        // outputs per warp
#define TILE       (WARPS * WTILE)            // 1024 outputs per block
#define TILES_ROW  ((W_OUT + TILE - 1) / TILE)  // 256
#define WLOAD      (WTILE + 32)               // 288 samples per warp (halo + 1 pad)
// padded index: one extra float2 per 8 elements -> conflict-free window LDS.64
#define PAD(i)     ((i) + ((i) >> 3))
#define SEG        324                        // float2 slots per warp segment (PAD(287)=322)

#define OUT_SCALE  0.17782794100389228f      // sqrt(10^(-15/10))

// ---- packed f32x2 helpers (Blackwell FFMA2 path) ----
__device__ __forceinline__ void upk2(unsigned long long v, float& lo, float& hi) {
    asm("mov.b64 {%0, %1}, %2;" : "=f"(lo), "=f"(hi) : "l"(v));
}
__device__ __forceinline__ unsigned long long ffma2(unsigned long long a,
                                                    unsigned long long b,
                                                    unsigned long long c) {
    unsigned long long d;
    asm("fma.rn.f32x2 %0, %1, %2, %3;" : "=l"(d) : "l"(a), "l"(b), "l"(c));
    return d;
}
__device__ __forceinline__ float tanh_approx(float x) {
    float y;
    asm("tanh.approx.f32 %0, %1;" : "=f"(y) : "f"(x));
    return y;
}
__device__ __forceinline__ unsigned long long lds64(const float2* p) {
    return *reinterpret_cast<const unsigned long long*>(p);
}

__global__ void __launch_bounds__(THREADS, 6)
hammer_wiener_kernel(const float* __restrict__ x_real,
                     const float* __restrict__ x_imag,
                     const float* __restrict__ w1_pre,
                     const float* __restrict__ w2_pre,
                     const float* __restrict__ w_fir_r,
                     const float* __restrict__ w_fir_i,
                     const float* __restrict__ w1_post,
                     const float* __restrict__ b1_post,
                     const float* __restrict__ w2_post,
                     const float* __restrict__ b2_post,
                     float2* __restrict__ out) {
    __shared__ float2 s_xh[WARPS * SEG];     // per-warp packed (xh_r, xh_i) windows
    __shared__ float2 s_wrb[FILTER_LEN];     // (wr, wr)
    __shared__ float2 s_wib[FILTER_LEN];     // (wi, wi)
    __shared__ float  s_w1a[8];
    __shared__ float  s_w2a[8];
    __shared__ float  s_w1b[8];
    __shared__ float  s_b1b[8];
    __shared__ float  s_w2b[8];
    __shared__ float  s_b2b;

    const int tid    = threadIdx.x;
    const int lane   = tid & 31;
    const int wrp    = tid >> 5;
    const int b      = blockIdx.y;
    const int tile0  = blockIdx.x * TILE;
    const int wstart = tile0 + wrp * WTILE;   // first output/sample of this warp

    // ---- params -> shared (only block-wide barrier in the kernel) ----
    if (tid < FILTER_LEN) {
        float wr = w_fir_r[tid];
        float wi = w_fir_i[tid];
        s_wrb[tid] = make_float2(wr, wr);
        s_wib[tid] = make_float2(wi, wi);
    }
    if (tid >= 32 && tid < 40) {
        int j = tid - 32;
        s_w1a[j] = w1_pre[j];
        s_w2a[j] = w2_pre[j];
        s_w1b[j] = w1_post[j];
        s_b1b[j] = b1_post[j];
        s_w2b[j] = w2_post[j];
    }
    if (tid == 40) s_b2b = b2_post[0];
    __syncthreads();

    float2* __restrict__ seg = s_xh + wrp * SEG;

    // ---- stage A: pre nonlinearity -> per-warp window (288 samples, 9/lane) ----
    const float* __restrict__ xr_row = x_real + (size_t)b * W_IN;
    const float* __restrict__ xi_row = x_imag + (size_t)b * W_IN;

    float rv[9], iv[9];
#pragma unroll
    for (int t = 0; t < 9; t++) {
        int g = wstart + lane + 32 * t;
        bool ok = (g < W_IN);
        rv[t] = ok ? xr_row[g] : 0.0f;
        iv[t] = ok ? xi_row[g] : 0.0f;
    }
#pragma unroll
    for (int t = 0; t < 9; t++) {
        float r = rv[t], im = iv[t];
        float m2  = fmaf(r, r, im * im);
        float inv = rsqrtf(m2);
        bool  nz  = (m2 > 0.0f);
        float mag = nz ? m2 * inv : 0.0f;
        float acc = 0.0f;
#pragma unroll
        for (int j = 0; j < 8; j++)
            acc = fmaf(tanh_approx(mag * s_w1a[j]), s_w2a[j], acc);
        float sc = nz ? acc * inv : 0.0f;       // m / mag
        int i = lane + 32 * t;
        seg[PAD(i)] = make_float2(sc * r, sc * im);
    }
    __syncwarp();

    // ---- stage B: 32-tap complex FIR, ring-buffer window (8 live elements) ----
    // acc1 = (sum wr*xr, sum wr*xi), acc2 = (sum wi*xr, sum wi*xi)
    const int base = lane * T_OUT;

    unsigned long long Wd[8];
#pragma unroll
    for (int i = 0; i < 8; i++) Wd[i] = lds64(&seg[PAD(base + i)]);

    unsigned long long acc1[T_OUT], acc2[T_OUT];
#pragma unroll
    for (int j = 0; j < T_OUT; j++) { acc1[j] = 0ULL; acc2[j] = 0ULL; }

#pragma unroll
    for (int k = 0; k < FILTER_LEN; k++) {
        unsigned long long wrb = lds64(&s_wrb[k]);
        unsigned long long wib = lds64(&s_wib[k]);
#pragma unroll
        for (int j = 0; j < T_OUT; j++) {
            unsigned long long a = Wd[(k + j) & 7];
            acc1[j] = ffma2(wrb, a, acc1[j]);
            acc2[j] = ffma2(wib, a, acc2[j]);
        }
        if (k < FILTER_LEN - 1)
            Wd[k & 7] = lds64(&seg[PAD(base + k + 8)]);
    }

    // ---- stage C: post nonlinearity + store ----
    const size_t out_base = (size_t)b * W_OUT;
    const int    n0       = wstart + base;
#pragma unroll
    for (int j = 0; j < T_OUT; j++) {
        float a1lo, a1hi, a2lo, a2hi;
        upk2(acc1[j], a1lo, a1hi);
        upk2(acc2[j], a2lo, a2hi);
        float zr = a1lo - a2hi;
        float zi = a1hi + a2lo;

        float m2  = fmaf(zr, zr, zi * zi);
        float inv = rsqrtf(m2);
        bool  nz  = (m2 > 0.0f);
        float zmag = nz ? m2 * inv : 0.0f;
        float cr   = nz ? zr * inv : 1.0f;   // cos(atan2(0,0)) = 1
        float ci   = nz ? zi * inv : 0.0f;

        float zm = s_b2b;
#pragma unroll
        for (int f = 0; f < 8; f++) {
            float g = fmaf(zmag, s_w1b[f], s_b1b[f]);
            g = fmaxf(g, 0.0f);
            zm = fmaf(g, s_w2b[f], zm);
        }
        float sm = OUT_SCALE * zm;

        int n = n0 + j;
        if (n < W_OUT) {
            out[out_base + n] = make_float2(sm * cr, sm * ci);
        }
    }
}

extern "C" void kernel_launch(void* const* d_in, const int* in_sizes, int n_in,
                              void* d_out, int out_size) {
    (void)in_sizes; (void)n_in; (void)out_size;
    const float* x_real   = (const float*)d_in[0];
    const float* x_imag   = (const float*)d_in[1];
    const float* w1_pre   = (const float*)d_in[2];
    const float* w2_pre   = (const float*)d_in[3];
    const float* w_fir_r  = (const float*)d_in[4];
    const float* w_fir_i  = (const float*)d_in[5];
    const float* w1_post  = (const float*)d_in[6];
    const float* b1_post  = (const float*)d_in[7];
    const float* w2_post  = (const float*)d_in[8];
    const float* b2_post  = (const float*)d_in[9];

    dim3 grid(TILES_ROW, BATCH);
    hammer_wiener_kernel<<<grid, THREADS>>>(
        x_real, x_imag, w1_pre, w2_pre, w_fir_r, w_fir_i,
        w1_post, b1_post, w2_post, b2_post, (float2*)d_out);
}